// round 16
// baseline (speedup 1.0000x reference)
#include <cuda_runtime.h>
#include <cuda_bf16.h>
#include <cstdint>

#define BB 32
#define CC 80
#define HH 128
#define WW 128
#define HWSZ (HH * WW)      // 16384
#define KK 100
#define CAP 196608          // per-batch candidate cap (expected ~156K survivors)

// Static device scratch (allocation-free per harness rules)
__device__ unsigned int g_cnt[BB];          // candidate counts
__device__ unsigned int g_done[BB];         // per-batch completion tickets
__device__ float    g_val[(size_t)BB * CAP];   // 24 MB
__device__ unsigned g_idx[(size_t)BB * CAP];   // 24 MB

// ---------------------------------------------------------------------------
// Load one row (float4 per lane), compute horizontal 3-max per component.
__device__ __forceinline__ void ldrow(const float4* __restrict__ fp4, int y, int cg,
                                      float4& f4, float4& hm) {
    const float NEG = -1e30f;
    f4 = fp4[y * 32 + cg];
    float left  = __shfl_up_sync(0xffffffffu, f4.w, 1);
    float right = __shfl_down_sync(0xffffffffu, f4.x, 1);
    if (cg == 0)  left  = NEG;
    if (cg == 31) right = NEG;
    hm.x = fmaxf(fmaxf(left, f4.x), f4.y);
    hm.y = fmaxf(fmaxf(f4.x, f4.y), f4.z);
    hm.z = fmaxf(fmaxf(f4.y, f4.z), f4.w);
    hm.w = fmaxf(fmaxf(f4.z, f4.w), right);
}

// ---------------------------------------------------------------------------
__global__ __launch_bounds__(512) void k_fused(const float* __restrict__ fmap,
                                               const float* __restrict__ wh,
                                               const float* __restrict__ reg,
                                               float* __restrict__ out) {
    __shared__ int s_whist[8][256];
    __shared__ int s_hist[256];
    __shared__ unsigned long long s_keys[1024];
    __shared__ int s_byte, s_above, s_bucket, s_wcnt, s_tk;

    const int plane = blockIdx.x;
    const int b = plane / CC;
    const int c = plane % CC;
    const float* __restrict__ fp = fmap + (size_t)plane * HWSZ;
    const float4* __restrict__ fp4 = (const float4*)fp;

    const int t = threadIdx.x;
    const int lane = t & 31;

    // ---------------- stage 1: pure-register NMS -----------------
    const int cg = t & 31;            // column group (4 consecutive x)
    const int y0 = (t >> 5) * 8;      // first row of this thread's segment
    const float NEG = -1e30f;

    float4 fcur, fnext;
    float4 hA, hB, hC;
    if (y0 == 0) {
        hA = make_float4(NEG, NEG, NEG, NEG);
    } else {
        float4 d; ldrow(fp4, y0 - 1, cg, d, hA);
    }
    ldrow(fp4, y0, cg, fcur, hB);
    ldrow(fp4, y0 + 1, cg, fnext, hC);

    unsigned mask = 0u;               // survivor bits: r*4 + q
#pragma unroll
    for (int r = 0; r < 8; r++) {
        const int y = y0 + r;
        float4 fnn, hD;
        if (r < 7) {
            if (y + 2 <= HH - 1) { ldrow(fp4, y + 2, cg, fnn, hD); }
            else { hD = make_float4(NEG, NEG, NEG, NEG); fnn = fnext; }
        }
        float4 vm;
        vm.x = fmaxf(fmaxf(hA.x, hB.x), hC.x);
        vm.y = fmaxf(fmaxf(hA.y, hB.y), hC.y);
        vm.z = fmaxf(fmaxf(hA.z, hB.z), hC.z);
        vm.w = fmaxf(fmaxf(hA.w, hB.w), hC.w);

        mask |= (unsigned)(fcur.x >= vm.x) << (r * 4 + 0);
        mask |= (unsigned)(fcur.y >= vm.y) << (r * 4 + 1);
        mask |= (unsigned)(fcur.z >= vm.z) << (r * 4 + 2);
        mask |= (unsigned)(fcur.w >= vm.w) << (r * 4 + 3);

        hA = hB; hB = hC;
        if (r < 7) { hC = hD; fcur = fnext; fnext = fnn; }
    }

    // ---------------- warp-aggregated append (once per warp) -----------------
    {
        int cnt = __popc(mask);
        // inclusive shfl scan of cnt within warp (uniform, full-warp)
        int incl = cnt;
#pragma unroll
        for (int off = 1; off < 32; off <<= 1) {
            int v = __shfl_up_sync(0xffffffffu, incl, off);
            if (lane >= off) incl += v;
        }
        unsigned base = 0;
        if (lane == 31) base = atomicAdd(&g_cnt[b], (unsigned)incl);
        base = __shfl_sync(0xffffffffu, base, 31);
        unsigned my = base + (unsigned)(incl - cnt);   // exclusive offset

        unsigned m = mask;
        while (m) {
            int bit = __ffs(m) - 1; m &= m - 1;
            int r = bit >> 2, q = bit & 3;
            int pos = (y0 + r) * WW + cg * 4 + q;
            if (my < CAP) {
                g_val[(size_t)b * CAP + my] = fp[pos];              // L1 hit
                g_idx[(size_t)b * CAP + my] = (unsigned)c * HWSZ + (unsigned)pos;
            }
            my++;
        }
    }

    // ---------------- completion ticket ----------------
    __threadfence();
    __syncthreads();
    if (t == 0) s_tk = (int)atomicAdd(&g_done[b], 1u);
    __syncthreads();
    if (s_tk != CC - 1) return;

    // ---------------- stage 2 (last block of batch b) ----------------
    __threadfence();   // acquire: other blocks' candidate writes visible

    const int M = min((int)g_cnt[b], CAP);
    const float*    __restrict__ cv = g_val + (size_t)b * CAP;
    const unsigned* __restrict__ ci = g_idx + (size_t)b * CAP;
    const int w = t >> 6;             // 8 sub-histograms

    unsigned T = 0u;
    {
        unsigned prefix = 0u, prefmask = 0u;
        int k = KK;
        int cnt_ge = M;
        for (int p = 3; p >= 0 && cnt_ge > 1024; p--) {
            for (int i = t; i < 8 * 256; i += 512) ((int*)s_whist)[i] = 0;
            __syncthreads();
            const int sh = p * 8;
            for (int i = t; i < M; i += 512) {         // no warp collectives inside
                unsigned v = __float_as_uint(cv[i]);
                if ((v & prefmask) == prefix)
                    atomicAdd(&s_whist[w][(v >> sh) & 255], 1);
            }
            __syncthreads();
            if (t < 256) {
                int s = 0;
#pragma unroll
                for (int j = 0; j < 8; j++) s += s_whist[j][t];
                s_hist[t] = s;
            }
            __syncthreads();
            if (t < 32) {              // warp0: suffix-scan 256 bins, crossing
                const int base = t * 8;
                int s = 0;
#pragma unroll
                for (int j = 0; j < 8; j++) s += s_hist[base + j];
                int suf = s;
#pragma unroll
                for (int off = 1; off < 32; off <<= 1) {
                    int v = __shfl_down_sync(0xffffffffu, suf, off);
                    if (t + off < 32) suf += v;
                }
                int sufN = __shfl_down_sync(0xffffffffu, suf, 1);
                if (t == 31) sufN = 0;
                if (suf >= k && sufN < k) {
                    int acc = sufN;
                    for (int j = 7; j >= 0; j--) {
                        acc += s_hist[base + j];
                        if (acc >= k) {
                            s_byte = base + j;
                            s_above = acc - s_hist[base + j];
                            s_bucket = s_hist[base + j];
                            break;
                        }
                    }
                }
            }
            __syncthreads();
            prefix |= ((unsigned)s_byte) << sh;
            prefmask |= 0xFFu << sh;
            k -= s_above;
            cnt_ge = (KK - k) + s_bucket;
            __syncthreads();
        }
        T = prefix;                    // |{v >= T}| == cnt_ge (<= 1024 normally)
    }

    // collect {v >= T} into shared keys — plain predicated atomics (~400 hits
    // out of M; NO warp collectives in this non-uniform-trip loop: the R13
    // ballot here deadlocked when lanes' trip counts differed on M % 512 != 0)
    if (t == 0) s_wcnt = 0;
    __syncthreads();
    for (int i = t; i < M; i += 512) {
        unsigned vb = __float_as_uint(cv[i]);
        if (vb >= T) {
            int s = atomicAdd(&s_wcnt, 1);
            if (s < 1024)
                s_keys[s] = ((unsigned long long)vb << 32) |
                            (unsigned long long)(0xFFFFFFFFu - ci[i]);
        }
    }
    __syncthreads();
    const int n = min(s_wcnt, 1024);

    // Rank-based exact top-K: unique 64-bit keys -> unique ranks
    unsigned long long my0 = 0ull, my1 = 0ull;
    int r0 = 0, r1 = 0;
    const bool h0 = (t < n), h1 = (t + 512 < n);
    if (h0) my0 = s_keys[t];
    if (h1) my1 = s_keys[t + 512];
    for (int j = 0; j < n; j++) {      // uniform trip count across block
        unsigned long long kj = s_keys[j];   // broadcast read
        r0 += (kj > my0);
        r1 += (kj > my1);
    }

    const float* __restrict__ whb = wh + (size_t)b * 2 * HWSZ;
    const float* __restrict__ regb = reg + (size_t)b * 2 * HWSZ;
#pragma unroll
    for (int e = 0; e < 2; e++) {
        bool have = e ? h1 : h0;
        int rk = e ? r1 : r0;
        unsigned long long key = e ? my1 : my0;
        if (have && rk < KK) {
            float val = __uint_as_float((unsigned)(key >> 32));
            unsigned pidx = 0xFFFFFFFFu - (unsigned)(key & 0xFFFFFFFFull);
            int cls = (int)(pidx >> 14);
            int pos = (int)(pidx & (HWSZ - 1));
            float yy = (float)(pos >> 7);
            float xx = (float)(pos & (WW - 1));
            float rx = regb[pos];
            float ry = regb[HWSZ + pos];
            float bw = whb[pos];
            float bh = whb[HWSZ + pos];
            float fx = xx + rx, fy = yy + ry;
            float hw2 = bw * 0.5f, hh2 = bh * 0.5f;
            float* bo = out + (size_t)(b * KK + rk) * 4;
            bo[0] = fx - hw2;
            bo[1] = fy - hh2;
            bo[2] = fx + hw2;
            bo[3] = fy + hh2;
            out[BB * KK * 4 + b * KK + rk] = val;                  // scores
            out[BB * KK * 4 + BB * KK + b * KK + rk] = (float)cls; // classes
        }
    }

    __syncthreads();
    if (t == 0) { g_cnt[b] = 0u; g_done[b] = 0u; }   // reset for next replay
}

// ---------------------------------------------------------------------------
extern "C" void kernel_launch(void* const* d_in, const int* in_sizes, int n_in,
                              void* d_out, int out_size) {
    const float* fmap = (const float*)d_in[0];
    const float* wh   = (const float*)d_in[1];
    const float* reg  = (const float*)d_in[2];
    float* out = (float*)d_out;

    k_fused<<<BB * CC, 512>>>(fmap, wh, reg, out);
}